// round 10
// baseline (speedup 1.0000x reference)
#include <cuda_runtime.h>
#include <cuda_fp16.h>
#include <cstdint>

#define BD 8
#define SD 2048
#define DD 1024
#define HD 1024
#define ED 2048
#define MD (BD * SD)
#define LAYERS 4

#define M_TILE 128
#define N_TILE 256
#define K_CHUNK 64
#define NCHUNK (DD / K_CHUNK)     // 16
#define XBLK (ED / N_TILE)        // 8
#define TILES (SD / M_TILE)       // 16
#define NCHAIN (BD * XBLK)        // 64

#define ROW_B 144
#define A_TILE_B (128 * ROW_B)
#define W_TILE_B (256 * ROW_B)
#define A_OFF 0
#define W_OFF A_TILE_B
#define STAGE_B (A_TILE_B + W_TILE_B)   // 55296
#define NSTAGE 3
#define SMEM_TOTAL (NSTAGE * STAGE_B)   // 165888
#define EPI_PITCH 132                   // half2 pitch (128 pairs + pad)

__device__ __half g_s0[(size_t)MD * HD];
__device__ __half g_s1[(size_t)MD * HD];
__device__ __half g_wh[(size_t)LAYERS * ED * DD];   // interleaved rows
// decoupled-lookback state
__device__ float g_aggA[NCHAIN * TILES * 128];
__device__ float g_aggC[NCHAIN * TILES * 128];
__device__ float g_pref[NCHAIN * TILES * 128];
__device__ int   g_flag[LAYERS * NCHAIN * TILES];

__device__ __forceinline__ uint32_t smem_u32(const void* p) {
    uint32_t a;
    asm("{ .reg .u64 t; cvta.to.shared.u64 t, %1; cvt.u32.u64 %0, t; }"
        : "=r"(a) : "l"(p));
    return a;
}
__device__ __forceinline__ void cp16(uint32_t dst, const void* src) {
    asm volatile("cp.async.cg.shared.global [%0], [%1], 16;" :: "r"(dst), "l"(src));
}
__device__ __forceinline__ void ldsm4(uint32_t* r, uint32_t addr) {
    asm volatile("ldmatrix.sync.aligned.m8n8.x4.shared.b16 {%0,%1,%2,%3}, [%4];"
                 : "=r"(r[0]), "=r"(r[1]), "=r"(r[2]), "=r"(r[3]) : "r"(addr));
}
__device__ __forceinline__ void mma16816(float* c, const uint32_t* a,
                                         uint32_t b0, uint32_t b1) {
    asm volatile(
        "mma.sync.aligned.m16n8k16.row.col.f32.f16.f16.f32 "
        "{%0,%1,%2,%3}, {%4,%5,%6,%7}, {%8,%9}, {%0,%1,%2,%3};"
        : "+f"(c[0]), "+f"(c[1]), "+f"(c[2]), "+f"(c[3])
        : "r"(a[0]), "r"(a[1]), "r"(a[2]), "r"(a[3]), "r"(b0), "r"(b1));
}
__device__ __forceinline__ int ld_acq(const int* p) {
    int v;
    asm volatile("ld.acquire.gpu.b32 %0, [%1];" : "=r"(v) : "l"(p));
    return v;
}
__device__ __forceinline__ void st_rel(int* p, int v) {
    asm volatile("st.release.gpu.b32 [%0], %1;" :: "l"(p), "r"(v));
}
__device__ __forceinline__ float sigf(float x) { return 1.f / (1.f + __expf(-x)); }
__device__ __forceinline__ float gact(float x) { return (x >= 0.f) ? (x + 0.5f) : sigf(x); }

// ---------------------------------------------------------------------------
// Fused GEMM + minGRU scan (decoupled lookback) + residual + stream write.
// W rows interleaved: row 2h = gate_h, row 2h+1 = hidden_h.
// ---------------------------------------------------------------------------
__global__ __launch_bounds__(256, 1) void gemm_scan(
    const __half* __restrict__ A, const __half* __restrict__ W,
    const float* __restrict__ bias,       // original layout (2H)
    const void* __restrict__ resid,       // fp32 x (layer0) or half stream
    const float* __restrict__ h0,         // (B, H)
    void* __restrict__ outp,              // half stream or fp32 final out
    float* __restrict__ finals,           // (B, H)
    int* __restrict__ flags,              // this layer's [NCHAIN*TILES]
    int ip_f32, int out_f32)
{
    extern __shared__ char smem[];
    __shared__ int s_state;
    const uint32_t sbase = smem_u32(smem);
    const int tid  = threadIdx.x;
    const int wid  = tid >> 5;
    const int lane = tid & 31;
    const int g    = lane >> 2;
    const int t4   = lane & 3;
    const int wm   = wid >> 2;
    const int wn   = wid & 3;
    const int bm   = blockIdx.y * M_TILE;
    const int bn   = blockIdx.x * N_TILE;

    float acc[4][8][4];
#pragma unroll
    for (int i = 0; i < 4; i++)
#pragma unroll
        for (int j = 0; j < 8; j++)
#pragma unroll
            for (int q = 0; q < 4; q++) acc[i][j][q] = 0.f;

    auto fill = [&](int s, int c) {
        const uint32_t st = sbase + s * STAGE_B;
        const int k0 = c * K_CHUNK;
#pragma unroll
        for (int rep = 0; rep < 4; rep++) {
            const int v  = tid + rep * 256;
            const int r  = v >> 3, c8 = v & 7;
            cp16(st + A_OFF + r * ROW_B + c8 * 16,
                 A + (size_t)(bm + r) * DD + k0 + c8 * 8);
        }
#pragma unroll
        for (int rep = 0; rep < 8; rep++) {
            const int v  = tid + rep * 256;
            const int r  = v >> 3, c8 = v & 7;
            cp16(st + W_OFF + r * ROW_B + c8 * 16,
                 W + (size_t)(bn + r) * DD + k0 + c8 * 8);
        }
        asm volatile("cp.async.commit_group;" ::: "memory");
    };

    const uint32_t a_off = (uint32_t)(wm * 64 + (lane & 15)) * ROW_B
                         + ((lane >> 4) & 1) * 16;
    const uint32_t w_mi  = (uint32_t)(lane >> 3);
    const uint32_t w_off = (uint32_t)(wn * 64 + (w_mi >> 1) * 8 + (lane & 7)) * ROW_B
                         + (w_mi & 1) * 16;

    fill(0, 0);
    fill(1, 1);

#pragma unroll 1
    for (int c = 0; c < NCHUNK; c++) {
        if (c + 1 < NCHUNK)
            asm volatile("cp.async.wait_group 1;" ::: "memory");
        else
            asm volatile("cp.async.wait_group 0;" ::: "memory");
        __syncthreads();

        if (c + 2 < NCHUNK) fill((c + 2) % NSTAGE, c + 2);

        const uint32_t st = sbase + (c % NSTAGE) * STAGE_B;
#pragma unroll
        for (int k16 = 0; k16 < 4; k16++) {
            const uint32_t kb = (uint32_t)k16 * 32;
            uint32_t wf[4][4];
#pragma unroll
            for (int jp = 0; jp < 4; jp++)
                ldsm4(wf[jp], st + W_OFF + w_off + jp * (16 * ROW_B) + kb);
#pragma unroll
            for (int mi = 0; mi < 4; mi++) {
                uint32_t af[4];
                ldsm4(af, st + A_OFF + a_off + mi * (16 * ROW_B) + kb);
#pragma unroll
                for (int jp = 0; jp < 4; jp++) {
                    mma16816(acc[mi][jp * 2],     af, wf[jp][0], wf[jp][1]);
                    mma16816(acc[mi][jp * 2 + 1], af, wf[jp][2], wf[jp][3]);
                }
            }
        }
    }
    __syncthreads();   // all LDSM reads of last stage done before smem reuse

    // ---- epilogue: stage (gate,hid) half2 pairs with bias in smem ----
    __half2* epi = (__half2*)smem;
    {
        float bg[8], bh[8];
#pragma unroll
        for (int j = 0; j < 8; j++) {
            const int c2 = wn * 32 + j * 4 + t4;          // pair index in CTA
            bg[j] = bias[bn / 2 + c2];
            bh[j] = bias[HD + bn / 2 + c2];
        }
#pragma unroll
        for (int mi = 0; mi < 4; mi++) {
            const int r1 = wm * 64 + mi * 16 + g;
#pragma unroll
            for (int j = 0; j < 8; j++) {
                const int cp = wn * 32 + j * 4 + t4;
                epi[(size_t)r1 * EPI_PITCH + cp] =
                    __floats2half2_rn(acc[mi][j][0] + bg[j], acc[mi][j][1] + bh[j]);
                epi[(size_t)(r1 + 8) * EPI_PITCH + cp] =
                    __floats2half2_rn(acc[mi][j][2] + bg[j], acc[mi][j][3] + bh[j]);
            }
        }
    }
    __syncthreads();

    // ---- scan over the 128-step window ----
    const int b     = blockIdx.y >> 4;          // batch
    const int ty    = blockIdx.y & 15;          // tile in chain
    const int chain = b * XBLK + blockIdx.x;
    const int t     = tid & 127;
    const int h     = bn / 2 + t;               // global hidden index
    const int idx   = (chain * TILES + ty) * 128 + t;
    int* flagp      = flags + chain * TILES;

    // phase 1: local composite
    float Aa = 1.f, Cc = 0.f;
    if (tid < 128) {
#pragma unroll 4
        for (int j = 0; j < 128; j++) {
            const float2 gh2 = __half22float2(epi[(size_t)j * EPI_PITCH + t]);
            const float z = sigf(gh2.x);
            const float a = 1.f - z;
            Cc = fmaf(a, Cc, z * gact(gh2.y));
            Aa *= a;
        }
        g_aggA[idx] = Aa; g_aggC[idx] = Cc;
    }
    __threadfence();
    __syncthreads();
    if (tid == 0) st_rel(flagp + ty, 1);

    // phase 2: lookback -> incoming prefix
    float hin = 0.f;
    if (ty == 0) {
        if (tid < 128) hin = gact(h0[b * HD + h]);
    } else {
        float accA = 1.f, accC = 0.f;
        int j2 = ty - 1;
        while (true) {
            if (tid == 0) {
                const int need = (j2 == 0) ? 2 : 1;
                int f;
                do { f = ld_acq(flagp + j2); } while (f < need);
                s_state = f;
            }
            __syncthreads();
            const int f = s_state;
            __syncthreads();
            const int jdx = (chain * TILES + j2) * 128 + t;
            if (f >= 2) {
                if (tid < 128) hin = fmaf(accA, g_pref[jdx], accC);
                break;
            }
            if (tid < 128) {
                accC = fmaf(accA, g_aggC[jdx], accC);
                accA *= g_aggA[jdx];
            }
            j2--;
        }
    }

    // phase 3: publish inclusive prefix ASAP
    if (tid < 128) g_pref[idx] = fmaf(Aa, hin, Cc);
    __threadfence();
    __syncthreads();
    if (tid == 0) st_rel(flagp + ty, 2);

    // phase 4: replay + residual + output
    if (tid < 128) {
        float hcur = hin;
        const size_t mbase = (size_t)bm * HD + h;
#pragma unroll 4
        for (int j = 0; j < 128; j++) {
            const float2 gh2 = __half22float2(epi[(size_t)j * EPI_PITCH + t]);
            const float z = sigf(gh2.x);
            hcur = fmaf(1.f - z, hcur, z * gact(gh2.y));
            const size_t gi = mbase + (size_t)j * HD;
            const float ip = ip_f32 ? ((const float*)resid)[gi]
                                    : __half2float(((const __half*)resid)[gi]);
            const float o = hcur + ip;
            if (out_f32) ((float*)outp)[gi] = o;
            else         ((__half*)outp)[gi] = __float2half_rn(o);
        }
        if (ty == TILES - 1) finals[b * HD + h] = hcur;
    }
}

// ---------------------------------------------------------------------------
__global__ void init_flags() {
    const int n = LAYERS * NCHAIN * TILES;
    for (int i = blockIdx.x * blockDim.x + threadIdx.x; i < n;
         i += gridDim.x * blockDim.x)
        g_flag[i] = 0;
}

__global__ __launch_bounds__(256) void conv_x(
    const float* __restrict__ src, __half* __restrict__ dst, size_t n)
{
    for (size_t i = (size_t)blockIdx.x * blockDim.x + threadIdx.x; i < n;
         i += (size_t)gridDim.x * blockDim.x)
        dst[i] = __float2half_rn(src[i]);
}

// interleave W rows: new row 2h = orig gate row h; new row 2h+1 = orig row H+h
__global__ __launch_bounds__(256) void conv_w(
    const float* __restrict__ W0, const float* __restrict__ Wl,
    __half* __restrict__ dst)
{
    const size_t per = (size_t)ED * DD;
    const size_t n = (size_t)LAYERS * per;
    for (size_t i = (size_t)blockIdx.x * blockDim.x + threadIdx.x; i < n;
         i += (size_t)gridDim.x * blockDim.x) {
        const int l = (int)(i / per);
        const size_t rem = i % per;
        const int nr = (int)(rem / DD);
        const int k  = (int)(rem % DD);
        const int orig = (nr & 1) ? (HD + (nr >> 1)) : (nr >> 1);
        const size_t si = (size_t)orig * DD + k;
        dst[i] = __float2half_rn((l == 0) ? W0[si] : Wl[(size_t)(l - 1) * per + si]);
    }
}

// ---------------------------------------------------------------------------
extern "C" void kernel_launch(void* const* d_in, const int* in_sizes, int n_in,
                              void* d_out, int out_size)
{
    const float* x  = (const float*)d_in[0];
    const float* h  = (const float*)d_in[1];
    const float* W0 = (const float*)d_in[2];
    const float* b0 = (const float*)d_in[3];
    const float* Wl = (const float*)d_in[4];
    const float* bl = (const float*)d_in[5];

    float* out    = (float*)d_out;
    float* finals = out + (size_t)MD * HD;

    __half *s0, *s1, *wh;
    int* flags;
    cudaGetSymbolAddress((void**)&s0, g_s0);
    cudaGetSymbolAddress((void**)&s1, g_s1);
    cudaGetSymbolAddress((void**)&wh, g_wh);
    cudaGetSymbolAddress((void**)&flags, g_flag);

    cudaFuncSetAttribute(gemm_scan, cudaFuncAttributeMaxDynamicSharedMemorySize,
                         SMEM_TOTAL);

    init_flags<<<4, 256>>>();
    conv_w<<<512, 256>>>(W0, Wl, wh);
    conv_x<<<512, 256>>>(x, s0, (size_t)MD * DD);

    const dim3 ggrid(XBLK, MD / M_TILE);   // (8, 128)

    __half* Astream[LAYERS + 1] = { s0, s1, s0, s1, s0 };
    for (int l = 0; l < LAYERS; l++) {
        const size_t woff = (size_t)l * ED * DD;
        const float* bb = (l == 0) ? b0 : bl + (size_t)(l - 1) * ED;
        const int last = (l == LAYERS - 1);

        gemm_scan<<<ggrid, 256, SMEM_TOTAL>>>(
            Astream[l], wh + woff, bb,
            (l == 0) ? (const void*)x : (const void*)Astream[l],
            h + (size_t)l * BD * HD,
            last ? (void*)out : (void*)Astream[l + 1],
            finals + (size_t)l * BD * HD,
            flags + l * NCHAIN * TILES,
            (l == 0) ? 1 : 0, last ? 1 : 0);
    }
}

// round 11
// speedup vs baseline: 2.6959x; 2.6959x over previous
#include <cuda_runtime.h>
#include <cuda_fp16.h>
#include <cstdint>

#define BD 8
#define SD 2048
#define DD 1024
#define HD 1024
#define ED 2048
#define MD (BD * SD)
#define LAYERS 4

#define M_TILE 128
#define N_TILE 256
#define K_CHUNK 64
#define NCHUNK (DD / K_CHUNK)     // 16

#define ROW_B 144                 // 128B data + 16B pad: conflict-free LDSM
#define A_TILE_B (128 * ROW_B)
#define W_TILE_B (256 * ROW_B)
#define A_OFF 0
#define W_OFF A_TILE_B
#define STAGE_B (A_TILE_B + W_TILE_B)   // 55296
#define NSTAGE 3
#define SMEM_TOTAL (NSTAGE * STAGE_B)   // 165888

__device__ __half g_gh[(size_t)MD * ED];
__device__ __half g_s0[(size_t)MD * HD];
__device__ __half g_s1[(size_t)MD * HD];
__device__ __half g_wh[(size_t)LAYERS * ED * DD];

__device__ __forceinline__ uint32_t smem_u32(const void* p) {
    uint32_t a;
    asm("{ .reg .u64 t; cvta.to.shared.u64 t, %1; cvt.u32.u64 %0, t; }"
        : "=r"(a) : "l"(p));
    return a;
}
__device__ __forceinline__ void cp16(uint32_t dst, const void* src) {
    asm volatile("cp.async.cg.shared.global [%0], [%1], 16;" :: "r"(dst), "l"(src));
}
__device__ __forceinline__ void ldsm4(uint32_t* r, uint32_t addr) {
    asm volatile("ldmatrix.sync.aligned.m8n8.x4.shared.b16 {%0,%1,%2,%3}, [%4];"
                 : "=r"(r[0]), "=r"(r[1]), "=r"(r[2]), "=r"(r[3]) : "r"(addr));
}
__device__ __forceinline__ void mma16816(float* c, const uint32_t* a,
                                         uint32_t b0, uint32_t b1) {
    asm volatile(
        "mma.sync.aligned.m16n8k16.row.col.f32.f16.f16.f32 "
        "{%0,%1,%2,%3}, {%4,%5,%6,%7}, {%8,%9}, {%0,%1,%2,%3};"
        : "+f"(c[0]), "+f"(c[1]), "+f"(c[2]), "+f"(c[3])
        : "r"(a[0]), "r"(a[1]), "r"(a[2]), "r"(a[3]), "r"(b0), "r"(b1));
}

// ---------------------------------------------------------------------------
// GEMM (R9): CTA 128x256, 8 warps (2x4), warp 64x64, K_CHUNK=64, 3-stage ring.
// ---------------------------------------------------------------------------
__global__ __launch_bounds__(256, 1) void gemm_mma(
    const __half* __restrict__ A, const __half* __restrict__ W,
    const float* __restrict__ bias, __half* __restrict__ C)
{
    extern __shared__ char smem[];
    const uint32_t sbase = smem_u32(smem);
    const int tid  = threadIdx.x;
    const int wid  = tid >> 5;
    const int lane = tid & 31;
    const int g    = lane >> 2;
    const int t4   = lane & 3;
    const int wm   = wid >> 2;
    const int wn   = wid & 3;
    const int bm   = blockIdx.y * M_TILE;
    const int bn   = blockIdx.x * N_TILE;

    float acc[4][8][4];
#pragma unroll
    for (int i = 0; i < 4; i++)
#pragma unroll
        for (int j = 0; j < 8; j++)
#pragma unroll
            for (int q = 0; q < 4; q++) acc[i][j][q] = 0.f;

    auto fill = [&](int s, int c) {
        const uint32_t st = sbase + s * STAGE_B;
        const int k0 = c * K_CHUNK;
#pragma unroll
        for (int rep = 0; rep < 4; rep++) {
            const int v  = tid + rep * 256;
            const int r  = v >> 3, c8 = v & 7;
            cp16(st + A_OFF + r * ROW_B + c8 * 16,
                 A + (size_t)(bm + r) * DD + k0 + c8 * 8);
        }
#pragma unroll
        for (int rep = 0; rep < 8; rep++) {
            const int v  = tid + rep * 256;
            const int r  = v >> 3, c8 = v & 7;
            cp16(st + W_OFF + r * ROW_B + c8 * 16,
                 W + (size_t)(bn + r) * DD + k0 + c8 * 8);
        }
        asm volatile("cp.async.commit_group;" ::: "memory");
    };

    const uint32_t a_off = (uint32_t)(wm * 64 + (lane & 15)) * ROW_B
                         + ((lane >> 4) & 1) * 16;
    const uint32_t w_mi  = (uint32_t)(lane >> 3);
    const uint32_t w_off = (uint32_t)(wn * 64 + (w_mi >> 1) * 8 + (lane & 7)) * ROW_B
                         + (w_mi & 1) * 16;

    fill(0, 0);
    fill(1, 1);

#pragma unroll 1
    for (int c = 0; c < NCHUNK; c++) {
        if (c + 1 < NCHUNK)
            asm volatile("cp.async.wait_group 1;" ::: "memory");
        else
            asm volatile("cp.async.wait_group 0;" ::: "memory");
        __syncthreads();

        if (c + 2 < NCHUNK) fill((c + 2) % NSTAGE, c + 2);

        const uint32_t st = sbase + (c % NSTAGE) * STAGE_B;
#pragma unroll
        for (int k16 = 0; k16 < 4; k16++) {
            const uint32_t kb = (uint32_t)k16 * 32;
            uint32_t wf[4][4];
#pragma unroll
            for (int jp = 0; jp < 4; jp++)
                ldsm4(wf[jp], st + W_OFF + w_off + jp * (16 * ROW_B) + kb);
#pragma unroll
            for (int mi = 0; mi < 4; mi++) {
                uint32_t af[4];
                ldsm4(af, st + A_OFF + a_off + mi * (16 * ROW_B) + kb);
#pragma unroll
                for (int jp = 0; jp < 4; jp++) {
                    mma16816(acc[mi][jp * 2],     af, wf[jp][0], wf[jp][1]);
                    mma16816(acc[mi][jp * 2 + 1], af, wf[jp][2], wf[jp][3]);
                }
            }
        }
    }

    float bj[8][2];
#pragma unroll
    for (int j = 0; j < 8; j++) {
        const int col = bn + wn * 64 + j * 8 + 2 * t4;
        bj[j][0] = bias[col]; bj[j][1] = bias[col + 1];
    }
#pragma unroll
    for (int mi = 0; mi < 4; mi++) {
        const int r0 = bm + wm * 64 + mi * 16 + g;
#pragma unroll
        for (int j = 0; j < 8; j++) {
            const int col = bn + wn * 64 + j * 8 + 2 * t4;
            __half2 v0 = __floats2half2_rn(acc[mi][j][0] + bj[j][0],
                                           acc[mi][j][1] + bj[j][1]);
            __half2 v1 = __floats2half2_rn(acc[mi][j][2] + bj[j][0],
                                           acc[mi][j][3] + bj[j][1]);
            *(__half2*)(C + (size_t)r0 * ED + col)       = v0;
            *(__half2*)(C + (size_t)(r0 + 8) * ED + col) = v1;
        }
    }
}

// ---------------------------------------------------------------------------
__global__ __launch_bounds__(256) void conv_x(
    const float* __restrict__ src, __half* __restrict__ dst, size_t n)
{
    for (size_t i = (size_t)blockIdx.x * blockDim.x + threadIdx.x; i < n;
         i += (size_t)gridDim.x * blockDim.x)
        dst[i] = __float2half_rn(src[i]);
}

__global__ __launch_bounds__(256) void conv_w(
    const float* __restrict__ W0, const float* __restrict__ Wl,
    __half* __restrict__ dst)
{
    const size_t per = (size_t)ED * DD;
    const size_t n = (size_t)LAYERS * per;
    for (size_t i = (size_t)blockIdx.x * blockDim.x + threadIdx.x; i < n;
         i += (size_t)gridDim.x * blockDim.x)
        dst[i] = __float2half_rn((i < per) ? W0[i] : Wl[i - per]);
}

// ---------------------------------------------------------------------------
// Scan half2 (R9 grid) with MUFU.TANH sigmoid: sigma(x) = 0.5*tanh(x/2)+0.5
// ---------------------------------------------------------------------------
__device__ __forceinline__ float sigf(float x) {
    float t;
    asm("tanh.approx.f32 %0, %1;" : "=f"(t) : "f"(0.5f * x));
    return fmaf(0.5f, t, 0.5f);
}
__device__ __forceinline__ float gact(float x) { return (x >= 0.f) ? (x + 0.5f) : sigf(x); }

#define SC_LANES 16
#define SC_NC    64
#define SC_CH    (SD / SC_NC)   // 32

__global__ __launch_bounds__(1024) void scan_h2(
    const __half2* __restrict__ gh,
    const void* __restrict__ inp,
    const float* __restrict__ h0,
    void* __restrict__ outp,
    float* __restrict__ finals, int ip_f32, int out_f32)
{
    const int b  = blockIdx.y;
    const int hx = threadIdx.x & (SC_LANES - 1);
    const int tc = threadIdx.x / SC_LANES;
    const int p  = blockIdx.x * SC_LANES + hx;
    const int t0 = tc * SC_CH;

    const size_t rowbase = (size_t)b * SD;
    const __half2* gp = gh + (rowbase + t0) * (ED / 2) + p;
    const __half2* hp = gp + HD / 2;

    float2 Ac = {1.f, 1.f}, Cc = {0.f, 0.f};
#pragma unroll 8
    for (int j = 0; j < SC_CH; j++) {
        const size_t off = (size_t)j * (ED / 2);
        const float2 zg  = __half22float2(gp[off]);
        const float2 hid = __half22float2(hp[off]);
        const float zx = sigf(zg.x), zy = sigf(zg.y);
        const float ax = 1.f - zx, ay = 1.f - zy;
        Cc.x = fmaf(ax, Cc.x, zx * gact(hid.x));
        Cc.y = fmaf(ay, Cc.y, zy * gact(hid.y));
        Ac.x *= ax; Ac.y *= ay;
    }

    __shared__ float2 sA[SC_NC][SC_LANES + 1], sC[SC_NC][SC_LANES + 1];
    sA[tc][hx] = Ac; sC[tc][hx] = Cc;
    __syncthreads();

    const float2 hprev = *(const float2*)(h0 + b * HD + 2 * p);
    float2 hcur = { gact(hprev.x), gact(hprev.y) };
    for (int c = 0; c < tc; c++) {
        const float2 a = sA[c][hx], cc = sC[c][hx];
        hcur.x = fmaf(a.x, hcur.x, cc.x);
        hcur.y = fmaf(a.y, hcur.y, cc.y);
    }

    const size_t obase = (rowbase + t0) * (HD / 2) + p;
#pragma unroll 8
    for (int j = 0; j < SC_CH; j++) {
        const size_t off = (size_t)j * (ED / 2);
        const float2 zg  = __half22float2(gp[off]);
        const float2 hid = __half22float2(hp[off]);
        const float zx = sigf(zg.x), zy = sigf(zg.y);
        hcur.x = fmaf(1.f - zx, hcur.x, zx * gact(hid.x));
        hcur.y = fmaf(1.f - zy, hcur.y, zy * gact(hid.y));

        const size_t idx = obase + (size_t)j * (HD / 2);
        float2 ipv;
        if (ip_f32) ipv = ((const float2*)inp)[idx];
        else        ipv = __half22float2(((const __half2*)inp)[idx]);
        const float2 o = { hcur.x + ipv.x, hcur.y + ipv.y };
        if (out_f32) ((float2*)outp)[idx] = o;
        else         ((__half2*)outp)[idx] = __floats2half2_rn(o.x, o.y);
    }
    if (tc == SC_NC - 1) *(float2*)(finals + b * HD + 2 * p) = hcur;
}

// ---------------------------------------------------------------------------
extern "C" void kernel_launch(void* const* d_in, const int* in_sizes, int n_in,
                              void* d_out, int out_size)
{
    const float* x  = (const float*)d_in[0];
    const float* h  = (const float*)d_in[1];
    const float* W0 = (const float*)d_in[2];
    const float* b0 = (const float*)d_in[3];
    const float* Wl = (const float*)d_in[4];
    const float* bl = (const float*)d_in[5];

    float* out    = (float*)d_out;
    float* finals = out + (size_t)MD * HD;

    __half *gh, *s0, *s1, *wh;
    cudaGetSymbolAddress((void**)&gh, g_gh);
    cudaGetSymbolAddress((void**)&s0, g_s0);
    cudaGetSymbolAddress((void**)&s1, g_s1);
    cudaGetSymbolAddress((void**)&wh, g_wh);

    cudaFuncSetAttribute(gemm_mma, cudaFuncAttributeMaxDynamicSharedMemorySize,
                         SMEM_TOTAL);

    conv_w<<<512, 256>>>(W0, Wl, wh);
    conv_x<<<512, 256>>>(x, s0, (size_t)MD * DD);

    const dim3 ggrid(ED / N_TILE, MD / M_TILE);         // (8, 128)
    const dim3 sgrid(HD / 2 / SC_LANES, BD);            // (32, 8)

    __half* Astream[LAYERS + 1] = { s0, s1, s0, s1, s0 };
    for (int l = 0; l < LAYERS; l++) {
        const size_t woff = (size_t)l * ED * DD;
        const float* bb = (l == 0) ? b0 : bl + (size_t)(l - 1) * ED;
        const int last = (l == LAYERS - 1);

        gemm_mma<<<ggrid, 256, SMEM_TOTAL>>>(Astream[l], wh + woff, bb, gh);
        scan_h2<<<sgrid, 1024>>>(
            (const __half2*)gh,
            (l == 0) ? (const void*)x : (const void*)Astream[l],
            h + (size_t)l * BD * HD,
            last ? (void*)out : (void*)Astream[l + 1],
            finals + (size_t)l * BD * HD,
            (l == 0) ? 1 : 0, last ? 1 : 0);
    }
}

// round 12
// speedup vs baseline: 2.8767x; 1.0671x over previous
#include <cuda_runtime.h>
#include <cuda_fp16.h>
#include <cstdint>

#define BD 8
#define SD 2048
#define DD 1024
#define HD 1024
#define ED 2048
#define MD (BD * SD)
#define LAYERS 4

#define M_TILE 128
#define N_TILE 128
#define K_CHUNK 64
#define NCHUNK (DD / K_CHUNK)     // 16

#define ROW_B 144                 // 128B data + 16B pad
#define A_TILE_B (128 * ROW_B)    // 18432
#define W_TILE_B (128 * ROW_B)    // 18432
#define A_OFF 0
#define W_OFF A_TILE_B
#define STAGE_B (A_TILE_B + W_TILE_B)   // 36864
#define NSTAGE 3
#define SMEM_TOTAL (NSTAGE * STAGE_B)   // 110592 -> 2 CTAs/SM

__device__ __half g_gh[(size_t)MD * ED];
__device__ __half g_s0[(size_t)MD * HD];
__device__ __half g_s1[(size_t)MD * HD];
__device__ __half g_wh[(size_t)LAYERS * ED * DD];

__device__ __forceinline__ uint32_t smem_u32(const void* p) {
    uint32_t a;
    asm("{ .reg .u64 t; cvta.to.shared.u64 t, %1; cvt.u32.u64 %0, t; }"
        : "=r"(a) : "l"(p));
    return a;
}
__device__ __forceinline__ void cp16(uint32_t dst, const void* src) {
    asm volatile("cp.async.cg.shared.global [%0], [%1], 16;" :: "r"(dst), "l"(src));
}
__device__ __forceinline__ void ldsm4(uint32_t* r, uint32_t addr) {
    asm volatile("ldmatrix.sync.aligned.m8n8.x4.shared.b16 {%0,%1,%2,%3}, [%4];"
                 : "=r"(r[0]), "=r"(r[1]), "=r"(r[2]), "=r"(r[3]) : "r"(addr));
}
__device__ __forceinline__ void mma16816(float* c, const uint32_t* a,
                                         uint32_t b0, uint32_t b1) {
    asm volatile(
        "mma.sync.aligned.m16n8k16.row.col.f32.f16.f16.f32 "
        "{%0,%1,%2,%3}, {%4,%5,%6,%7}, {%8,%9}, {%0,%1,%2,%3};"
        : "+f"(c[0]), "+f"(c[1]), "+f"(c[2]), "+f"(c[3])
        : "r"(a[0]), "r"(a[1]), "r"(a[2]), "r"(a[3]), "r"(b0), "r"(b1));
}

// ---------------------------------------------------------------------------
// GEMM: CTA 128x128, 8 warps (2 wm x 4 wn), warp 64x32, K_CHUNK=64,
// 3-stage cp.async ring, 2 CTAs/SM.
// ---------------------------------------------------------------------------
__global__ __launch_bounds__(256, 2) void gemm_mma(
    const __half* __restrict__ A, const __half* __restrict__ W,
    const float* __restrict__ bias, __half* __restrict__ C)
{
    extern __shared__ char smem[];
    const uint32_t sbase = smem_u32(smem);
    const int tid  = threadIdx.x;
    const int wid  = tid >> 5;
    const int lane = tid & 31;
    const int g    = lane >> 2;
    const int t4   = lane & 3;
    const int wm   = wid >> 2;        // 0..1 : 64 m-rows
    const int wn   = wid & 3;         // 0..3 : 32 n-cols
    const int bm   = blockIdx.y * M_TILE;
    const int bn   = blockIdx.x * N_TILE;

    float acc[4][4][4];               // [m16][n8][quad]
#pragma unroll
    for (int i = 0; i < 4; i++)
#pragma unroll
        for (int j = 0; j < 4; j++)
#pragma unroll
            for (int q = 0; q < 4; q++) acc[i][j][q] = 0.f;

    auto fill = [&](int s, int c) {
        const uint32_t st = sbase + s * STAGE_B;
        const int k0 = c * K_CHUNK;
#pragma unroll
        for (int rep = 0; rep < 4; rep++) {           // A: 128 rows x 8 chunks
            const int v  = tid + rep * 256;
            const int r  = v >> 3, c8 = v & 7;
            cp16(st + A_OFF + r * ROW_B + c8 * 16,
                 A + (size_t)(bm + r) * DD + k0 + c8 * 8);
        }
#pragma unroll
        for (int rep = 0; rep < 4; rep++) {           // W: 128 rows x 8 chunks
            const int v  = tid + rep * 256;
            const int r  = v >> 3, c8 = v & 7;
            cp16(st + W_OFF + r * ROW_B + c8 * 16,
                 W + (size_t)(bn + r) * DD + k0 + c8 * 8);
        }
        asm volatile("cp.async.commit_group;" ::: "memory");
    };

    const uint32_t a_off = (uint32_t)(wm * 64 + (lane & 15)) * ROW_B
                         + ((lane >> 4) & 1) * 16;
    const uint32_t w_mi  = (uint32_t)(lane >> 3);
    const uint32_t w_off = (uint32_t)(wn * 32 + (w_mi >> 1) * 8 + (lane & 7)) * ROW_B
                         + (w_mi & 1) * 16;

    fill(0, 0);
    fill(1, 1);

#pragma unroll 1
    for (int c = 0; c < NCHUNK; c++) {
        if (c + 1 < NCHUNK)
            asm volatile("cp.async.wait_group 1;" ::: "memory");
        else
            asm volatile("cp.async.wait_group 0;" ::: "memory");
        __syncthreads();

        if (c + 2 < NCHUNK) fill((c + 2) % NSTAGE, c + 2);

        const uint32_t st = sbase + (c % NSTAGE) * STAGE_B;
#pragma unroll
        for (int k16 = 0; k16 < 4; k16++) {
            const uint32_t kb = (uint32_t)k16 * 32;
            uint32_t wf[2][4];
#pragma unroll
            for (int jp = 0; jp < 2; jp++)
                ldsm4(wf[jp], st + W_OFF + w_off + jp * (16 * ROW_B) + kb);
#pragma unroll
            for (int mi = 0; mi < 4; mi++) {
                uint32_t af[4];
                ldsm4(af, st + A_OFF + a_off + mi * (16 * ROW_B) + kb);
#pragma unroll
                for (int jp = 0; jp < 2; jp++) {
                    mma16816(acc[mi][jp * 2],     af, wf[jp][0], wf[jp][1]);
                    mma16816(acc[mi][jp * 2 + 1], af, wf[jp][2], wf[jp][3]);
                }
            }
        }
    }

    float bj[4][2];
#pragma unroll
    for (int j = 0; j < 4; j++) {
        const int col = bn + wn * 32 + j * 8 + 2 * t4;
        bj[j][0] = bias[col]; bj[j][1] = bias[col + 1];
    }
#pragma unroll
    for (int mi = 0; mi < 4; mi++) {
        const int r0 = bm + wm * 64 + mi * 16 + g;
#pragma unroll
        for (int j = 0; j < 4; j++) {
            const int col = bn + wn * 32 + j * 8 + 2 * t4;
            __half2 v0 = __floats2half2_rn(acc[mi][j][0] + bj[j][0],
                                           acc[mi][j][1] + bj[j][1]);
            __half2 v1 = __floats2half2_rn(acc[mi][j][2] + bj[j][0],
                                           acc[mi][j][3] + bj[j][1]);
            *(__half2*)(C + (size_t)r0 * ED + col)       = v0;
            *(__half2*)(C + (size_t)(r0 + 8) * ED + col) = v1;
        }
    }
}

// ---------------------------------------------------------------------------
__global__ __launch_bounds__(256) void conv_x(
    const float* __restrict__ src, __half* __restrict__ dst, size_t n)
{
    for (size_t i = (size_t)blockIdx.x * blockDim.x + threadIdx.x; i < n;
         i += (size_t)gridDim.x * blockDim.x)
        dst[i] = __float2half_rn(src[i]);
}

__global__ __launch_bounds__(256) void conv_w(
    const float* __restrict__ W0, const float* __restrict__ Wl,
    __half* __restrict__ dst)
{
    const size_t per = (size_t)ED * DD;
    const size_t n = (size_t)LAYERS * per;
    for (size_t i = (size_t)blockIdx.x * blockDim.x + threadIdx.x; i < n;
         i += (size_t)gridDim.x * blockDim.x)
        dst[i] = __float2half_rn((i < per) ? W0[i] : Wl[i - per]);
}

// ---------------------------------------------------------------------------
// Scan half2 with MUFU.TANH sigmoid (R11).
// ---------------------------------------------------------------------------
__device__ __forceinline__ float sigf(float x) {
    float t;
    asm("tanh.approx.f32 %0, %1;" : "=f"(t) : "f"(0.5f * x));
    return fmaf(0.5f, t, 0.5f);
}
__device__ __forceinline__ float gact(float x) { return (x >= 0.f) ? (x + 0.5f) : sigf(x); }

#define SC_LANES 16
#define SC_NC    64
#define SC_CH    (SD / SC_NC)   // 32

__global__ __launch_bounds__(1024) void scan_h2(
    const __half2* __restrict__ gh,
    const void* __restrict__ inp,
    const float* __restrict__ h0,
    void* __restrict__ outp,
    float* __restrict__ finals, int ip_f32, int out_f32)
{
    const int b  = blockIdx.y;
    const int hx = threadIdx.x & (SC_LANES - 1);
    const int tc = threadIdx.x / SC_LANES;
    const int p  = blockIdx.x * SC_LANES + hx;
    const int t0 = tc * SC_CH;

    const size_t rowbase = (size_t)b * SD;
    const __half2* gp = gh + (rowbase + t0) * (ED / 2) + p;
    const __half2* hp = gp + HD / 2;

    float2 Ac = {1.f, 1.f}, Cc = {0.f, 0.f};
#pragma unroll 8
    for (int j = 0; j < SC_CH; j++) {
        const size_t off = (size_t)j * (ED / 2);
        const float2 zg  = __half22float2(gp[off]);
        const float2 hid = __half22float2(hp[off]);
        const float zx = sigf(zg.x), zy = sigf(zg.y);
        const float ax = 1.f - zx, ay = 1.f - zy;
        Cc.x = fmaf(ax, Cc.x, zx * gact(hid.x));
        Cc.y = fmaf(ay, Cc.y, zy * gact(hid.y));
        Ac.x *= ax; Ac.y *= ay;
    }

    __shared__ float2 sA[SC_NC][SC_LANES + 1], sC[SC_NC][SC_LANES + 1];
    sA[tc][hx] = Ac; sC[tc][hx] = Cc;
    __syncthreads();

    const float2 hprev = *(const float2*)(h0 + b * HD + 2 * p);
    float2 hcur = { gact(hprev.x), gact(hprev.y) };
    for (int c = 0; c < tc; c++) {
        const float2 a = sA[c][hx], cc = sC[c][hx];
        hcur.x = fmaf(a.x, hcur.x, cc.x);
        hcur.y = fmaf(a.y, hcur.y, cc.y);
    }

    const size_t obase = (rowbase + t0) * (HD / 2) + p;
#pragma unroll 8
    for (int j = 0; j < SC_CH; j++) {
        const size_t off = (size_t)j * (ED / 2);
        const float2 zg  = __half22float2(gp[off]);
        const float2 hid = __half22float2(hp[off]);
        const float zx = sigf(zg.x), zy = sigf(zg.y);
        hcur.x = fmaf(1.f - zx, hcur.x, zx * gact(hid.x));
        hcur.y = fmaf(1.f - zy, hcur.y, zy * gact(hid.y));

        const size_t idx = obase + (size_t)j * (HD / 2);
        float2 ipv;
        if (ip_f32) ipv = ((const float2*)inp)[idx];
        else        ipv = __half22float2(((const __half2*)inp)[idx]);
        const float2 o = { hcur.x + ipv.x, hcur.y + ipv.y };
        if (out_f32) ((float2*)outp)[idx] = o;
        else         ((__half2*)outp)[idx] = __floats2half2_rn(o.x, o.y);
    }
    if (tc == SC_NC - 1) *(float2*)(finals + b * HD + 2 * p) = hcur;
}

// ---------------------------------------------------------------------------
extern "C" void kernel_launch(void* const* d_in, const int* in_sizes, int n_in,
                              void* d_out, int out_size)
{
    const float* x  = (const float*)d_in[0];
    const float* h  = (const float*)d_in[1];
    const float* W0 = (const float*)d_in[2];
    const float* b0 = (const float*)d_in[3];
    const float* Wl = (const float*)d_in[4];
    const float* bl = (const float*)d_in[5];

    float* out    = (float*)d_out;
    float* finals = out + (size_t)MD * HD;

    __half *gh, *s0, *s1, *wh;
    cudaGetSymbolAddress((void**)&gh, g_gh);
    cudaGetSymbolAddress((void**)&s0, g_s0);
    cudaGetSymbolAddress((void**)&s1, g_s1);
    cudaGetSymbolAddress((void**)&wh, g_wh);

    cudaFuncSetAttribute(gemm_mma, cudaFuncAttributeMaxDynamicSharedMemorySize,
                         SMEM_TOTAL);

    conv_w<<<512, 256>>>(W0, Wl, wh);
    conv_x<<<512, 256>>>(x, s0, (size_t)MD * DD);

    const dim3 ggrid(ED / N_TILE, MD / M_TILE);         // (16, 128)
    const dim3 sgrid(HD / 2 / SC_LANES, BD);            // (32, 8)

    __half* Astream[LAYERS + 1] = { s0, s1, s0, s1, s0 };
    for (int l = 0; l < LAYERS; l++) {
        const size_t woff = (size_t)l * ED * DD;
        const float* bb = (l == 0) ? b0 : bl + (size_t)(l - 1) * ED;
        const int last = (l == LAYERS - 1);

        gemm_mma<<<ggrid, 256, SMEM_TOTAL>>>(Astream[l], wh + woff, bb, gh);
        scan_h2<<<sgrid, 1024>>>(
            (const __half2*)gh,
            (l == 0) ? (const void*)x : (const void*)Astream[l],
            h + (size_t)l * BD * HD,
            last ? (void*)out : (void*)Astream[l + 1],
            finals + (size_t)l * BD * HD,
            (l == 0) ? 1 : 0, last ? 1 : 0);
    }
}